// round 1
// baseline (speedup 1.0000x reference)
#include <cuda_runtime.h>
#include <math.h>

// DRMM: B=32, D=8, QL=16, DL=512, E=300, V=50000
// score[b,d] = ( sum_q softmax(q_emb@w_g)_q * ((sum_t w1[bin(cos(q,t))] + b1)*w2 + b2) ) * w_o + b_o
//
// One CTA per (b, doc) pair (n = b*8 + d), 256 threads.
// Register-tiled fp32 "GEMM": each thread computes a 4q x 4t tile of the
// [16 x 512] dot matrix, streaming doc-token embeddings through e-major smem.

#define EPSQ 1e-8f

namespace {
constexpr int QLn = 16;
constexpr int DLn = 512;
constexpr int En  = 300;
constexpr int Tn  = 256;   // tokens per tile (2 tiles)
constexpr int SP  = 260;   // padded ds smem stride
constexpr int ECMAX = 76;  // largest E chunk

// smem layout (floats)
constexpr int OFF_DS  = 0;                       // [ECMAX][SP] = 19760 (reused as red[16][64])
constexpr int OFF_QS  = 19760;                   // qsT [300][16] = 4800
constexpr int OFF_WG  = OFF_QS + 4800;           // 300
constexpr int OFF_DN2 = OFF_WG + 300;            // 256
constexpr int OFF_DNS = OFF_DN2 + 256;           // 256
constexpr int OFF_QNS = OFF_DNS + 256;           // 16
constexpr int OFF_TWS = OFF_QNS + 16;            // 16
constexpr int OFF_GTS = OFF_TWS + 16;            // 16
constexpr int OFF_FV  = OFF_GTS + 16;            // 16
constexpr int OFF_W1  = OFF_FV + 16;             // 8
constexpr int SMEM_FLOATS = OFF_W1 + 8;
constexpr int SMEM_BYTES  = SMEM_FLOATS * 4;     // ~101.8 KB
}

__global__ void __launch_bounds__(256, 2) drmm_kernel(
    const int*   __restrict__ bq,     // [32,16]
    const int*   __restrict__ bd,     // [32,8,512]
    const float* __restrict__ emb,    // [50000,300]
    const float* __restrict__ w_g,    // [300]
    const float* __restrict__ b_g,    // [1]
    const float* __restrict__ w1,     // [5]
    const float* __restrict__ b1,     // [1]
    const float* __restrict__ w2,     // [1]
    const float* __restrict__ b2,     // [1]
    const float* __restrict__ w_o,    // [1]
    const float* __restrict__ b_o,    // [1]
    float*       __restrict__ out)    // [32,8]
{
    extern __shared__ float sm[];
    float* dsc = sm + OFF_DS;
    float* qsT = sm + OFF_QS;
    float* wgs = sm + OFF_WG;
    float* dn2 = sm + OFF_DN2;
    float* dns = sm + OFF_DNS;
    float* qns = sm + OFF_QNS;
    float* tws = sm + OFF_TWS;
    float* gts = sm + OFF_GTS;
    float* fv  = sm + OFF_FV;
    float* w1s = sm + OFF_W1;

    const int tid = threadIdx.x;
    const int n   = blockIdx.x;
    const int b   = n >> 3;
    const int* qrow = bq + b * QLn;
    const int* drow = bd + n * DLn;

    if (tid < 5) w1s[tid] = w1[tid];
    for (int i = tid; i < En; i += 256) wgs[i] = w_g[i];

    // ---- gather query embeddings, transposed e-major ----
    {
        const int g = tid & 3, r = tid >> 2;
        if (r < QLn) {
            const int tok = qrow[r];
            const float4* src = (const float4*)(emb + (size_t)tok * En);
            for (int f = g; f < 75; f += 4) {
                float4 v = __ldg(src + f);
                const int e = f * 4;
                qsT[(e + 0) * 16 + r] = v.x;
                qsT[(e + 1) * 16 + r] = v.y;
                qsT[(e + 2) * 16 + r] = v.z;
                qsT[(e + 3) * 16 + r] = v.w;
            }
        }
    }
    __syncthreads();

    // ---- query norms + gate ----
    if (tid < QLn) {
        float s2 = 0.f, g = 0.f;
        for (int e = 0; e < En; e++) {
            const float v = qsT[e * 16 + tid];
            s2 = fmaf(v, v, s2);
            g  = fmaf(v, wgs[e], g);
        }
        qns[tid] = __fsqrt_rn(s2);
        gts[tid] = g + b_g[0];
    }
    __syncthreads();
    if (tid == 0) {   // softmax over 16 query terms
        float m = gts[0];
        for (int q = 1; q < QLn; q++) m = fmaxf(m, gts[q]);
        float den = 0.f;
        for (int q = 0; q < QLn; q++) { const float ex = expf(gts[q] - m); tws[q] = ex; den += ex; }
        for (int q = 0; q < QLn; q++) tws[q] /= den;
    }

    const int qg = tid >> 6;   // 0..3 : q block of 4
    const int t4 = tid & 63;   // 0..63: t block of 4
    float ws[4] = {0.f, 0.f, 0.f, 0.f};

    const int e0s[4] = {0, 76, 152, 228};
    const int ecs[4] = {76, 76, 76, 72};

    for (int tile = 0; tile < 2; tile++) {
        dn2[tid] = 0.f;
        float acc[4][4];
        #pragma unroll
        for (int j = 0; j < 4; j++)
            #pragma unroll
            for (int i = 0; i < 4; i++) acc[j][i] = 0.f;

        for (int c = 0; c < 4; c++) {
            __syncthreads();
            // gather E-chunk of 256 token rows, transposed into dsc
            const int e0 = e0s[c], nf4 = ecs[c] >> 2;
            const int g = tid & 3, r0 = tid >> 2;
            #pragma unroll
            for (int p = 0; p < 4; p++) {
                const int t   = r0 + p * 64;
                const int tok = drow[tile * Tn + t];
                const float4* src = (const float4*)(emb + (size_t)tok * En + e0);
                float sq = 0.f;
                for (int f = g; f < nf4; f += 4) {
                    const float4 v = __ldg(src + f);
                    sq = fmaf(v.x, v.x, sq); sq = fmaf(v.y, v.y, sq);
                    sq = fmaf(v.z, v.z, sq); sq = fmaf(v.w, v.w, sq);
                    const int e = f * 4;
                    dsc[(e + 0) * SP + t] = v.x;
                    dsc[(e + 1) * SP + t] = v.y;
                    dsc[(e + 2) * SP + t] = v.z;
                    dsc[(e + 3) * SP + t] = v.w;
                }
                sq += __shfl_xor_sync(0xffffffffu, sq, 1);
                sq += __shfl_xor_sync(0xffffffffu, sq, 2);
                if (g == 0) dn2[t] += sq;
            }
            __syncthreads();
            // register-tiled outer product: 4q x 4t per thread
            const float* qbase = qsT + e0 * 16 + qg * 4;
            const float* dbase = dsc + t4 * 4;
            const int ec = ecs[c];
            #pragma unroll 4
            for (int e = 0; e < ec; e++) {
                const float4 aq = *(const float4*)(qbase + e * 16);
                const float4 ad = *(const float4*)(dbase + e * SP);
                acc[0][0] = fmaf(aq.x, ad.x, acc[0][0]);
                acc[0][1] = fmaf(aq.x, ad.y, acc[0][1]);
                acc[0][2] = fmaf(aq.x, ad.z, acc[0][2]);
                acc[0][3] = fmaf(aq.x, ad.w, acc[0][3]);
                acc[1][0] = fmaf(aq.y, ad.x, acc[1][0]);
                acc[1][1] = fmaf(aq.y, ad.y, acc[1][1]);
                acc[1][2] = fmaf(aq.y, ad.z, acc[1][2]);
                acc[1][3] = fmaf(aq.y, ad.w, acc[1][3]);
                acc[2][0] = fmaf(aq.z, ad.x, acc[2][0]);
                acc[2][1] = fmaf(aq.z, ad.y, acc[2][1]);
                acc[2][2] = fmaf(aq.z, ad.z, acc[2][2]);
                acc[2][3] = fmaf(aq.z, ad.w, acc[2][3]);
                acc[3][0] = fmaf(aq.w, ad.x, acc[3][0]);
                acc[3][1] = fmaf(aq.w, ad.y, acc[3][1]);
                acc[3][2] = fmaf(aq.w, ad.z, acc[3][2]);
                acc[3][3] = fmaf(aq.w, ad.w, acc[3][3]);
            }
        }
        __syncthreads();
        dns[tid] = __fsqrt_rn(dn2[tid]);
        __syncthreads();

        // epilogue: cos -> bin -> += w1[bin]
        #pragma unroll
        for (int i = 0; i < 4; i++) {
            const float dn = dns[t4 * 4 + i];
            #pragma unroll
            for (int j = 0; j < 4; j++) {
                const float qn = qns[qg * 4 + j];
                const float cs = __fdiv_rn(acc[j][i], fmaxf(qn * dn, EPSQ));
                if (cs >= -1.0f && cs <= 1.0f) {
                    const float add = cs < -0.5f ? w1s[0]
                                    : cs <  0.0f ? w1s[1]
                                    : cs <  0.5f ? w1s[2]
                                    : cs <  1.0f ? w1s[3] : w1s[4];
                    ws[j] += add;
                }
            }
        }
    }

    // ---- deterministic reduction over t, then score ----
    __syncthreads();
    float* red = dsc;  // reuse: [16][64]
    #pragma unroll
    for (int j = 0; j < 4; j++) red[(qg * 4 + j) * 64 + t4] = ws[j];
    __syncthreads();
    if (tid < QLn) {
        float s = 0.f;
        for (int k = 0; k < 64; k++) s += red[tid * 64 + k];
        const float ffnn = (s + b1[0]) * w2[0] + b2[0];
        fv[tid] = ffnn * tws[tid];
    }
    __syncthreads();
    if (tid == 0) {
        float tot = 0.f;
        for (int q = 0; q < QLn; q++) tot += fv[q];
        out[n] = tot * w_o[0] + b_o[0];
    }
}

extern "C" void kernel_launch(void* const* d_in, const int* in_sizes, int n_in,
                              void* d_out, int out_size) {
    const int*   bq  = (const int*)  d_in[0];   // batch_queries [32,16]
    // d_in[1] query_len : unused by reference
    const int*   bd  = (const int*)  d_in[2];   // batch_docs [32,8,512]
    // d_in[3] doc_len : unused by reference
    const float* emb = (const float*)d_in[4];   // [50000,300]
    const float* wg  = (const float*)d_in[5];
    const float* bg  = (const float*)d_in[6];
    const float* w1  = (const float*)d_in[7];
    const float* b1  = (const float*)d_in[8];
    const float* w2  = (const float*)d_in[9];
    const float* b2  = (const float*)d_in[10];
    const float* wo  = (const float*)d_in[11];
    const float* bo  = (const float*)d_in[12];
    float* out = (float*)d_out;                 // [32,8]

    cudaFuncSetAttribute(drmm_kernel, cudaFuncAttributeMaxDynamicSharedMemorySize, SMEM_BYTES);
    drmm_kernel<<<256, 256, SMEM_BYTES>>>(bq, bd, emb, wg, bg, w1, b1, w2, b2, wo, bo, out);
}

// round 4
// speedup vs baseline: 1.3442x; 1.3442x over previous
#include <cuda_runtime.h>
#include <math.h>

// DRMM: B=32, D=8, QL=16, DL=512, E=300, V=50000
// One CTA per (b,doc) pair, 256 threads, 2 doc tokens per thread.
// Doc embeddings streamed from L2 (no smem staging); query tile in smem
// (q-major, broadcast LDS.128). Dot products via packed fma.rn.f32x2 over
// e-pairs: 16q x 2tok packed accumulators per thread.

#define EPSQ 1e-8f

namespace {
constexpr int QL = 16;
constexpr int DL = 512;
constexpr int E  = 300;
constexpr int NF = 75;   // float4 chunks per row
}

__device__ __forceinline__ void fma2(unsigned long long& d,
                                     unsigned long long a,
                                     unsigned long long b) {
    asm("fma.rn.f32x2 %0, %1, %2, %0;" : "+l"(d) : "l"(a), "l"(b));
}
__device__ __forceinline__ float psum(unsigned long long v) {
    return __uint_as_float((unsigned)v) + __uint_as_float((unsigned)(v >> 32));
}

__global__ void __launch_bounds__(256, 2) drmm_kernel(
    const int*   __restrict__ bq,     // [32,16]
    const int*   __restrict__ bd,     // [32,8,512]
    const float* __restrict__ emb,    // [50000,300]
    const float* __restrict__ w_g,    // [300]
    const float* __restrict__ b_g,
    const float* __restrict__ w1,     // [5]
    const float* __restrict__ b1,
    const float* __restrict__ w2,
    const float* __restrict__ b2,
    const float* __restrict__ w_o,
    const float* __restrict__ b_o,
    float*       __restrict__ out)    // [32,8]
{
    __shared__ float qs[QL * E];      // q-major query tile
    __shared__ float qns[QL], tws[QL], gts[QL], fv[QL];
    __shared__ float red[QL][8];
    __shared__ float w1s[5];

    const int tid = threadIdx.x;
    const int n   = blockIdx.x;
    const int b   = n >> 3;

    // ---- coop copy of 16 query rows (1200 float4) ----
    {
        const int* qrow = bq + b * QL;
        for (int i = tid; i < QL * NF; i += 256) {
            const int q = i / NF, f = i - q * NF;
            const int tok = qrow[q];
            ((float4*)qs)[q * NF + f] =
                __ldg((const float4*)(emb + (size_t)tok * E) + f);
        }
    }
    if (tid < 5) w1s[tid] = w1[tid];
    __syncthreads();

    // ---- query norms + gate (16 lanes per q, subwarp reduce) ----
    {
        const int q = tid >> 4, l16 = tid & 15;
        float s2 = 0.f, g = 0.f;
        const float* r = qs + q * E;
        for (int e = l16; e < E; e += 16) {
            const float v = r[e];
            s2 = fmaf(v, v, s2);
            g  = fmaf(v, __ldg(w_g + e), g);
        }
        #pragma unroll
        for (int k = 8; k >= 1; k >>= 1) {
            s2 += __shfl_xor_sync(0xffffffffu, s2, k, 16);
            g  += __shfl_xor_sync(0xffffffffu, g,  k, 16);
        }
        if (l16 == 0) { qns[q] = __fsqrt_rn(s2); gts[q] = g + b_g[0]; }
    }
    __syncthreads();
    if (tid == 0) {  // softmax over 16 query terms
        float m = gts[0];
        for (int q = 1; q < QL; q++) m = fmaxf(m, gts[q]);
        float den = 0.f;
        for (int q = 0; q < QL; q++) { const float ex = expf(gts[q] - m); tws[q] = ex; den += ex; }
        for (int q = 0; q < QL; q++) tws[q] /= den;
    }

    // ---- main loop: 2 doc tokens per thread, packed f32x2 FMA ----
    const int* drow = bd + n * DL;
    const int tok0 = drow[tid];
    const int tok1 = drow[tid + 256];
    const ulonglong2* p0 = (const ulonglong2*)(emb + (size_t)tok0 * E);
    const ulonglong2* p1 = (const ulonglong2*)(emb + (size_t)tok1 * E);

    unsigned long long acc[QL][2];
    #pragma unroll
    for (int q = 0; q < QL; q++) { acc[q][0] = 0ull; acc[q][1] = 0ull; }
    unsigned long long nr0 = 0ull, nr1 = 0ull;

    ulonglong2 c0 = __ldg(p0), c1 = __ldg(p1);
    #pragma unroll 1
    for (int f = 0; f < NF; f++) {
        ulonglong2 t0, t1;
        if (f + 1 < NF) { t0 = __ldg(p0 + f + 1); t1 = __ldg(p1 + f + 1); }
        fma2(nr0, c0.x, c0.x); fma2(nr0, c0.y, c0.y);
        fma2(nr1, c1.x, c1.x); fma2(nr1, c1.y, c1.y);
        const char* qb = (const char*)qs + f * 16;
        #pragma unroll
        for (int q = 0; q < QL; q++) {
            const ulonglong2 qv = *(const ulonglong2*)(qb + q * (E * 4));
            fma2(acc[q][0], qv.x, c0.x); fma2(acc[q][0], qv.y, c0.y);
            fma2(acc[q][1], qv.x, c1.x); fma2(acc[q][1], qv.y, c1.y);
        }
        c0 = t0; c1 = t1;
    }

    // ---- epilogue: cos -> bin -> w1[bin], per-thread partials ----
    const float dn0 = __fsqrt_rn(psum(nr0));
    const float dn1 = __fsqrt_rn(psum(nr1));
    float ws[QL];
    #pragma unroll
    for (int q = 0; q < QL; q++) {
        const float qn = qns[q];
        float s = 0.f;
        const float cs0 = __fdiv_rn(psum(acc[q][0]), fmaxf(qn * dn0, EPSQ));
        const float cs1 = __fdiv_rn(psum(acc[q][1]), fmaxf(qn * dn1, EPSQ));
        if (cs0 >= -1.0f && cs0 <= 1.0f) {
            s += cs0 < -0.5f ? w1s[0]
               : cs0 <  0.0f ? w1s[1]
               : cs0 <  0.5f ? w1s[2]
               : cs0 <  1.0f ? w1s[3] : w1s[4];
        }
        if (cs1 >= -1.0f && cs1 <= 1.0f) {
            s += cs1 < -0.5f ? w1s[0]
               : cs1 <  0.0f ? w1s[1]
               : cs1 <  0.5f ? w1s[2]
               : cs1 <  1.0f ? w1s[3] : w1s[4];
        }
        ws[q] = s;
    }

    // ---- deterministic reduction: warp shfl tree -> 8 partials -> 16 lanes ----
    const int lane = tid & 31, wid = tid >> 5;
    #pragma unroll
    for (int q = 0; q < QL; q++) {
        float v = ws[q];
        v += __shfl_xor_sync(0xffffffffu, v, 16);
        v += __shfl_xor_sync(0xffffffffu, v, 8);
        v += __shfl_xor_sync(0xffffffffu, v, 4);
        v += __shfl_xor_sync(0xffffffffu, v, 2);
        v += __shfl_xor_sync(0xffffffffu, v, 1);
        if (lane == 0) red[q][wid] = v;
    }
    __syncthreads();
    if (tid < QL) {
        float s = 0.f;
        #pragma unroll
        for (int k = 0; k < 8; k++) s += red[tid][k];
        fv[tid] = ((s + b1[0]) * w2[0] + b2[0]) * tws[tid];
    }
    __syncthreads();
    if (tid == 0) {
        float tot = 0.f;
        for (int q = 0; q < QL; q++) tot += fv[q];
        out[n] = tot * w_o[0] + b_o[0];
    }
}

extern "C" void kernel_launch(void* const* d_in, const int* in_sizes, int n_in,
                              void* d_out, int out_size) {
    const int*   bq  = (const int*)  d_in[0];   // batch_queries [32,16]
    const int*   bd  = (const int*)  d_in[2];   // batch_docs [32,8,512]
    const float* emb = (const float*)d_in[4];   // [50000,300]
    const float* wg  = (const float*)d_in[5];
    const float* bg  = (const float*)d_in[6];
    const float* w1  = (const float*)d_in[7];
    const float* b1  = (const float*)d_in[8];
    const float* w2  = (const float*)d_in[9];
    const float* b2  = (const float*)d_in[10];
    const float* wo  = (const float*)d_in[11];
    const float* bo  = (const float*)d_in[12];
    float* out = (float*)d_out;                 // [32,8]

    drmm_kernel<<<256, 256>>>(bq, bd, emb, wg, bg, w1, b1, w2, b2, wo, bo, out);
}